// round 15
// baseline (speedup 1.0000x reference)
#include <cuda_runtime.h>
#include <cuda_fp16.h>

// Problem constants
#define B_   4
#define IC   16      // inDim
#define S_   4096    // nSeq
#define O_   64      // outDim
#define W_   64      // nWin
#define OH   16      // outputs per CTA
#define TT   128     // time-tile per CTA (halved: Phase B splits o across 2 groups)
#define ECH  8       // events per chunk

// Shared memory (bytes):
//  wsm : fp16 [row=i*16+wq][o ^ (row&15)][4 halves] = 32768
//  trf : fp16 [e*64+w][20 halves, 16 used]          = 20480  at 32768
//  xs  : fp32 2 x 128                               at 53248
//  src : 2 x 8 ints                                 at 54272
#define TRF_OFF_B  32768
#define XS_OFF_B   (TRF_OFF_B + 512*20*2)     // 53248
#define SRC_OFF_B  (XS_OFF_B + 2*128*4)       // 54272
#define SMEM_BYTES (SRC_OFF_B + 64)           // 54336 B -> 4 CTAs/SM

__device__ __forceinline__ unsigned long long ffma2(unsigned long long a,
                                                    unsigned long long b,
                                                    unsigned long long c) {
    unsigned long long d;
    asm("fma.rn.f32x2 %0, %1, %2, %3;" : "=l"(d) : "l"(a), "l"(b), "l"(c));
    return d;
}
__device__ __forceinline__ unsigned long long add2(unsigned long long a,
                                                   unsigned long long b) {
    unsigned long long d;
    asm("add.rn.f32x2 %0, %1, %2;" : "=l"(d) : "l"(a), "l"(b));
    return d;
}
__device__ __forceinline__ unsigned long long pack2(float lo, float hi) {
    unsigned long long d;
    asm("mov.b64 %0, {%1, %2};" : "=l"(d) : "f"(lo), "f"(hi));
    return d;
}
__device__ __forceinline__ void unpack2(unsigned long long v, float& lo, float& hi) {
    asm("mov.b64 {%0, %1}, %2;" : "=f"(lo), "=f"(hi) : "l"(v));
}

__global__ __launch_bounds__(256, 4)
void astrf_kernel(const float* __restrict__ x, const float* __restrict__ wt,
                  const float* __restrict__ bias, const int* __restrict__ srcIdx,
                  float* __restrict__ out, int T)
{
    extern __shared__ char smemc[];
    uint2*  wsm2  = (uint2*)smemc;
    __half* trf   = (__half*)(smemc + TRF_OFF_B);
    float*  xs    = (float*)(smemc + XS_OFF_B);
    int*    srcsm = (int*)(smemc + SRC_OFF_B);

    const int tid   = threadIdx.x;
    const int b     = blockIdx.z;
    const int oBase = blockIdx.y * OH;
    const int t0    = blockIdx.x * TT;

    // ---- Stage weights: gmem f32 -> smem f16, XOR-swizzled (coalesced gmem).
    {
        const int lane = tid & 31;
        #pragma unroll
        for (int r = 0; r < 2; r++) {
            const int o = (tid >> 5) + r * 8;     // 0..15
            const float4* gw = (const float4*)(wt + (size_t)(oBase + o) * (IC * W_));
            #pragma unroll
            for (int u = 0; u < 8; u++) {
                int row = lane + u * 32;                   // 0..255 = i*16 + wq
                float4 v = gw[row];
                __half2 h01 = __floats2half2_rn(v.x, v.y);
                __half2 h23 = __floats2half2_rn(v.z, v.w);
                uint2 hv;
                hv.x = *(unsigned*)&h01; hv.y = *(unsigned*)&h23;
                wsm2[row * 16 + (o ^ (row & 15))] = hv;
            }
        }
    }

    // ---- Per-thread binary search for event window [t0-(W-1), t0+TT)
    int sLo, sHi;
    {
        const int* sp = srcIdx + b * S_;
        int lo = 0, hi = S_, tgt = t0 - (W_ - 1);
        while (lo < hi) { int m = (lo + hi) >> 1; if (sp[m] < tgt) lo = m + 1; else hi = m; }
        sLo = lo;
        lo = 0; hi = S_; tgt = t0 + TT;
        while (lo < hi) { int m = (lo + hi) >> 1; if (sp[m] < tgt) lo = m + 1; else hi = m; }
        sHi = lo;
    }

    // Thread roles
    const int oA  = tid & 15;            // Phase A: output lane
    const int wqA = tid >> 4;            // Phase A: w-quad (0..15)
    const int oh  = tid >> 7;            // Phase B: o-half (0/1)
    const int tlB = tid & 127;           // Phase B: time offset within tile

    // Phase-A weight pointer (swizzle term == wqA, constant per thread)
    const uint2* wA = wsm2 + wqA * 16 + (oA ^ wqA);

    // Persistent accumulators: 8 outputs as 4 f32x2 (o-half split)
    unsigned long long acc2[4];
    #pragma unroll
    for (int k = 0; k < 4; k++) acc2[k] = 0ull;

    // ---- x/src staging
    auto stage = [&](int c0, int buf) {
        if (tid < 128) {
            int i = tid >> 3, e = tid & 7;
            float v = (c0 + e < sHi) ? x[(size_t)(b * IC + i) * S_ + c0 + e] : 0.f;
            xs[buf * 128 + i * 8 + e] = v;
        } else if (tid < 136) {
            int k = tid - 128;
            srcsm[buf * 8 + k] = (c0 + k < sHi) ? srcIdx[b * S_ + c0 + k] : (1 << 29);
        }
    };
    stage(sLo, 0);
    __syncthreads();

    int cur = 0;
    for (int c0 = sLo; c0 < sHi; c0 += ECH) {
        // ---- Phase A: trf[e][w][o] = sum_i x[i,e] * w[o,i,w]
        // f32x2 lanes pair adjacent events; x pairs load directly (no dups).
        unsigned long long a2[4][4];
        #pragma unroll
        for (int k = 0; k < 4; k++)
            #pragma unroll
            for (int ep = 0; ep < 4; ep++) a2[k][ep] = 0ull;

        const float* xb = xs + cur * 128;
        #pragma unroll
        for (int i = 0; i < IC; i++) {
            uint2 hv = wA[i * 256];                        // conflict-free LDS.64
            float2 f01 = __half22float2(*(__half2*)&hv.x);
            float2 f23 = __half22float2(*(__half2*)&hv.y);
            unsigned long long wd0 = pack2(f01.x, f01.x);  // dup w taps
            unsigned long long wd1 = pack2(f01.y, f01.y);
            unsigned long long wd2 = pack2(f23.x, f23.x);
            unsigned long long wd3 = pack2(f23.y, f23.y);
            const ulonglong2* xp = (const ulonglong2*)(xb + i * 8);
            ulonglong2 xq0 = xp[0];                        // (e0,e1),(e2,e3)
            ulonglong2 xq1 = xp[1];                        // (e4,e5),(e6,e7)
            a2[0][0] = ffma2(wd0, xq0.x, a2[0][0]);
            a2[1][0] = ffma2(wd1, xq0.x, a2[1][0]);
            a2[2][0] = ffma2(wd2, xq0.x, a2[2][0]);
            a2[3][0] = ffma2(wd3, xq0.x, a2[3][0]);
            a2[0][1] = ffma2(wd0, xq0.y, a2[0][1]);
            a2[1][1] = ffma2(wd1, xq0.y, a2[1][1]);
            a2[2][1] = ffma2(wd2, xq0.y, a2[2][1]);
            a2[3][1] = ffma2(wd3, xq0.y, a2[3][1]);
            a2[0][2] = ffma2(wd0, xq1.x, a2[0][2]);
            a2[1][2] = ffma2(wd1, xq1.x, a2[1][2]);
            a2[2][2] = ffma2(wd2, xq1.x, a2[2][2]);
            a2[3][2] = ffma2(wd3, xq1.x, a2[3][2]);
            a2[0][3] = ffma2(wd0, xq1.y, a2[0][3]);
            a2[1][3] = ffma2(wd1, xq1.y, a2[1][3]);
            a2[2][3] = ffma2(wd2, xq1.y, a2[2][3]);
            a2[3][3] = ffma2(wd3, xq1.y, a2[3][3]);
        }
        // ---- Store trf fp16: rows (e*64 + w), stride 20 halves, col oA.
        // Disjoint 8-bank groups per STS.16 -> 1 phase each.
        #pragma unroll
        for (int ep = 0; ep < 4; ep++) {
            #pragma unroll
            for (int k = 0; k < 4; k++) {
                float fe0, fe1;
                unpack2(a2[k][ep], fe0, fe1);
                trf[((2*ep)     * 64 + wqA * 4 + k) * 20 + oA] = __float2half_rn(fe0);
                trf[((2*ep + 1) * 64 + wqA * 4 + k) * 20 + oA] = __float2half_rn(fe1);
            }
        }
        __syncthreads();   // trf ready; xs[cur] fully consumed

        // ---- Stage next chunk into the other buffer (overlaps Phase B)
        if (c0 + ECH < sHi) stage(c0 + ECH, cur ^ 1);

        // ---- Phase B: overlap-add; 2 conflict-free LDS.64 per event hit
        {
            const int t = t0 + tlB;
            const int* sp = srcsm + cur * 8;
            #pragma unroll
            for (int e = 0; e < ECH; e++) {
                int w = t - sp[e];
                if ((unsigned)w < (unsigned)W_) {
                    const uint2* rp =
                        (const uint2*)(trf + (e * 64 + w) * 20 + oh * 8);
                    uint2 v0 = rp[0];                      // halves o 0..3 of half
                    uint2 v1 = rp[1];                      // halves o 4..7 of half
                    float2 g0 = __half22float2(*(__half2*)&v0.x);
                    float2 g1 = __half22float2(*(__half2*)&v0.y);
                    float2 g2 = __half22float2(*(__half2*)&v1.x);
                    float2 g3 = __half22float2(*(__half2*)&v1.y);
                    acc2[0] = add2(acc2[0], pack2(g0.x, g0.y));
                    acc2[1] = add2(acc2[1], pack2(g1.x, g1.y));
                    acc2[2] = add2(acc2[2], pack2(g2.x, g2.y));
                    acc2[3] = add2(acc2[3], pack2(g3.x, g3.y));
                }
            }
        }
        __syncthreads();   // Phase B done reading trf; next x staged
        cur ^= 1;
    }

    // ---- Epilogue: bias + coalesced store (lanes = consecutive t)
    {
        const int t = t0 + tlB;
        #pragma unroll
        for (int j = 0; j < 4; j++) {
            float f0, f1;
            unpack2(acc2[j], f0, f1);
            int o0 = oBase + oh * 8 + 2 * j;
            out[(size_t)(b * O_ + o0) * T + t]     = f0 + __ldg(bias + o0);
            out[(size_t)(b * O_ + o0 + 1) * T + t] = f1 + __ldg(bias + o0 + 1);
        }
    }
}

extern "C" void kernel_launch(void* const* d_in, const int* in_sizes, int n_in,
                              void* d_out, int out_size) {
    (void)in_sizes; (void)n_in;
    const float* x    = (const float*)d_in[0];
    const float* wt   = (const float*)d_in[1];
    const float* bias = (const float*)d_in[2];
    const int*   src  = (const int*)d_in[3];
    float* out = (float*)d_out;

    int T = out_size / (B_ * O_);   // 32768
    cudaFuncSetAttribute(astrf_kernel, cudaFuncAttributeMaxDynamicSharedMemorySize, SMEM_BYTES);
    dim3 grid(T / TT, O_ / OH, B_);
    astrf_kernel<<<grid, 256, SMEM_BYTES>>>(x, wt, bias, src, out, T);
}